// round 4
// baseline (speedup 1.0000x reference)
#include <cuda_runtime.h>

// Problem constants (fixed by the dataset)
#define NN 50000
#define EE 800000
#define RRR 2
#define DD 128
#define GGG 64
#define CCC 8

// ---------------- device scratch (no allocations allowed) ----------------
__device__ __align__(256) float g_isd[RRR * NN];            // inv_sqrt_deg per relation
__device__ __align__(256) float g_xw[(size_t)RRR * NN * DD]; // h @ W[l,r] per relation
__device__ __align__(256) float g_acc[(size_t)NN * DD];      // aggregation accumulator
__device__ __align__(256) float g_h1[(size_t)NN * DD];       // relu output of layer 0
__device__ __align__(256) float g_pool[GGG * DD];            // per-graph sums
__device__ __align__(256) float g_cnt[GGG];                  // per-graph node counts

// ---------------- degree / normalization ----------------
__global__ void k_deg_init() {
    int i = blockIdx.x * blockDim.x + threadIdx.x;
    if (i < RRR * NN) g_isd[i] = 1.0f;   // self-loop contributes 1 to degree
}

__global__ void k_deg_count(const int* __restrict__ ei) {
    int r = blockIdx.y;
    int e = blockIdx.x * blockDim.x + threadIdx.x;
    if (e < EE) {
        int d = __ldg(ei + (size_t)r * 2 * EE + EE + e);   // dst
        atomicAdd(&g_isd[r * NN + d], 1.0f);
    }
}

__global__ void k_deg_rsqrt() {
    int i = blockIdx.x * blockDim.x + threadIdx.x;
    if (i < RRR * NN) g_isd[i] = rsqrtf(g_isd[i]);
}

// ---------------- SGEMM: xw[r] = h @ W[l,r]  (fp32, 128x128 tiles) ----------------
#define BM 128
#define BN 128
#define BK 8
#define TM 8
#define TN 8

__global__ __launch_bounds__(256) void k_gemm(const float* __restrict__ x,
                                              const float* __restrict__ W,
                                              int l) {
    __shared__ float As[BK][BM];
    __shared__ float Bs[BK][BN];

    const float* h = (l == 0) ? x : g_h1;
    int r = blockIdx.y;
    const float* Wr = W + ((size_t)(l * 2 + r)) * DD * DD;  // [128,128] row-major (k, j)
    float* out = g_xw + (size_t)r * NN * DD;

    int row0 = blockIdx.x * BM;
    int tid = threadIdx.x;

    int arow = tid >> 1;            // 0..127
    int acol = (tid & 1) * 4;       // 0 or 4
    int brow = tid >> 5;            // 0..7
    int bcol = (tid & 31) * 4;      // 0..124

    int tm = (tid >> 4) * TM;       // 0..120
    int tn = (tid & 15) * TN;       // 0..120

    float acc[TM][TN];
#pragma unroll
    for (int i = 0; i < TM; i++)
#pragma unroll
        for (int j = 0; j < TN; j++) acc[i][j] = 0.0f;

    for (int k0 = 0; k0 < DD; k0 += BK) {
        int gr = row0 + arow;
        float4 av = make_float4(0.f, 0.f, 0.f, 0.f);
        if (gr < NN) av = *(const float4*)(h + (size_t)gr * DD + k0 + acol);
        As[acol + 0][arow] = av.x;
        As[acol + 1][arow] = av.y;
        As[acol + 2][arow] = av.z;
        As[acol + 3][arow] = av.w;

        float4 bv = *(const float4*)(Wr + (size_t)(k0 + brow) * DD + bcol);
        *(float4*)&Bs[brow][bcol] = bv;

        __syncthreads();

#pragma unroll
        for (int k = 0; k < BK; k++) {
            float4 a0 = *(const float4*)&As[k][tm];
            float4 a1 = *(const float4*)&As[k][tm + 4];
            float4 b0 = *(const float4*)&Bs[k][tn];
            float4 b1 = *(const float4*)&Bs[k][tn + 4];
            float a[TM] = {a0.x, a0.y, a0.z, a0.w, a1.x, a1.y, a1.z, a1.w};
            float b[TN] = {b0.x, b0.y, b0.z, b0.w, b1.x, b1.y, b1.z, b1.w};
#pragma unroll
            for (int i = 0; i < TM; i++)
#pragma unroll
                for (int j = 0; j < TN; j++) acc[i][j] += a[i] * b[j];
        }
        __syncthreads();
    }

#pragma unroll
    for (int i = 0; i < TM; i++) {
        int gr = row0 + tm + i;
        if (gr < NN) {
            float4* p = (float4*)(out + (size_t)gr * DD + tn);
            p[0] = make_float4(acc[i][0], acc[i][1], acc[i][2], acc[i][3]);
            p[1] = make_float4(acc[i][4], acc[i][5], acc[i][6], acc[i][7]);
        }
    }
}

// ---------------- self-loop term + bias init of accumulator ----------------
__global__ void k_init_acc(const float* __restrict__ b, int l) {
    int idx = blockIdx.x * blockDim.x + threadIdx.x;
    if (idx >= NN * 32) return;
    int node = idx >> 5;
    int q = (idx & 31) * 4;
    float i0 = g_isd[node];
    float i1 = g_isd[NN + node];
    float c0 = i0 * i0, c1 = i1 * i1;
    float4 v0 = *(const float4*)&g_xw[(size_t)node * DD + q];
    float4 v1 = *(const float4*)&g_xw[((size_t)NN + node) * DD + q];
    const float* b0 = b + (size_t)(l * 2 + 0) * DD + q;
    const float* b1 = b + (size_t)(l * 2 + 1) * DD + q;
    float4 o;
    o.x = c0 * v0.x + c1 * v1.x + b0[0] + b1[0];
    o.y = c0 * v0.y + c1 * v1.y + b0[1] + b1[1];
    o.z = c0 * v0.z + c1 * v1.z + b0[2] + b1[2];
    o.w = c0 * v0.w + c1 * v1.w + b0[3] + b1[3];
    *(float4*)&g_acc[(size_t)node * DD + q] = o;
}

// ---------------- edge scatter: one warp per edge, vector reductions ----------------
__global__ __launch_bounds__(256) void k_scatter(const int* __restrict__ ei) {
    int r = blockIdx.y;
    int e = blockIdx.x * 8 + (threadIdx.x >> 5);
    if (e >= EE) return;
    int lane = threadIdx.x & 31;

    const int* srcp = ei + (size_t)r * 2 * EE;
    const int* dstp = srcp + EE;

    int s = 0, t = 0;
    float c = 0.f;
    if (lane == 0) {
        s = __ldg(srcp + e);
        t = __ldg(dstp + e);
        c = g_isd[r * NN + s] * g_isd[r * NN + t];
    }
    s = __shfl_sync(0xffffffffu, s, 0);
    t = __shfl_sync(0xffffffffu, t, 0);
    c = __shfl_sync(0xffffffffu, c, 0);

    float4 v = *(const float4*)&g_xw[((size_t)r * NN + s) * DD + lane * 4];
    float* p = &g_acc[(size_t)t * DD + lane * 4];
    asm volatile("red.global.add.v4.f32 [%0], {%1, %2, %3, %4};"
                 :: "l"(p), "f"(v.x * c), "f"(v.y * c), "f"(v.z * c), "f"(v.w * c)
                 : "memory");
}

// ---------------- relu epilogue (layer 0) ----------------
__global__ void k_relu() {
    int idx = blockIdx.x * blockDim.x + threadIdx.x;
    if (idx >= NN * 32) return;
    float4 v = *(const float4*)&g_acc[(size_t)idx * 4];
    v.x = fmaxf(v.x, 0.f);
    v.y = fmaxf(v.y, 0.f);
    v.z = fmaxf(v.z, 0.f);
    v.w = fmaxf(v.w, 0.f);
    *(float4*)&g_h1[(size_t)idx * 4] = v;
}

// ---------------- pooling ----------------
__global__ void k_pool_zero() {
    int i = blockIdx.x * blockDim.x + threadIdx.x;
    if (i < GGG * DD) g_pool[i] = 0.f;
    if (i < GGG) g_cnt[i] = 0.f;
}

#define POOL_CHUNK 256
__global__ void k_pool(const int* __restrict__ batch) {
    int d = threadIdx.x;                    // 0..127
    int n0 = blockIdx.x * POOL_CHUNK;
    if (n0 >= NN) return;
    int n1 = n0 + POOL_CHUNK;
    if (n1 > NN) n1 = NN;

    int cur = __ldg(batch + n0);
    float local = 0.f;
    float cl = 0.f;
    for (int n = n0; n < n1; n++) {
        int g = __ldg(batch + n);
        if (g != cur) {
            atomicAdd(&g_pool[cur * DD + d], local);
            if (d == 0) atomicAdd(&g_cnt[cur], cl);
            local = 0.f;
            cl = 0.f;
            cur = g;
        }
        local += g_acc[(size_t)n * DD + d];
        cl += 1.f;
    }
    atomicAdd(&g_pool[cur * DD + d], local);
    if (d == 0) atomicAdd(&g_cnt[cur], cl);
}

// ---------------- final linear on pooled means ----------------
__global__ void k_final(const float* __restrict__ lin_w,
                        const float* __restrict__ lin_b,
                        float* __restrict__ out) {
    int tid = threadIdx.x;
    if (tid >= GGG * CCC) return;
    int g = tid >> 3;
    int c = tid & 7;
    float inv = 1.0f / fmaxf(g_cnt[g], 1.0f);
    float s = 0.f;
#pragma unroll 4
    for (int d = 0; d < DD; d++) s += g_pool[g * DD + d] * lin_w[d * CCC + c];
    out[g * CCC + c] = s * inv + lin_b[c];
}

// ---------------- launch ----------------
extern "C" void kernel_launch(void* const* d_in, const int* in_sizes, int n_in,
                              void* d_out, int out_size) {
    const float* x     = (const float*)d_in[0];
    const float* W     = (const float*)d_in[1];
    const float* b     = (const float*)d_in[2];
    const float* lin_w = (const float*)d_in[3];
    const float* lin_b = (const float*)d_in[4];
    const int*   ei    = (const int*)d_in[5];
    const int*   batch = (const int*)d_in[6];
    float* out = (float*)d_out;

    // degrees -> inv_sqrt_deg
    k_deg_init<<<(RRR * NN + 255) / 256, 256>>>();
    dim3 gcnt((EE + 255) / 256, RRR);
    k_deg_count<<<gcnt, 256>>>(ei);
    k_deg_rsqrt<<<(RRR * NN + 255) / 256, 256>>>();

    dim3 ggemm((NN + BM - 1) / BM, RRR);
    dim3 gscat((EE + 7) / 8, RRR);
    int elem_blocks = (NN * 32 + 255) / 256;

    // layer 0
    k_gemm<<<ggemm, 256>>>(x, W, 0);
    k_init_acc<<<elem_blocks, 256>>>(b, 0);
    k_scatter<<<gscat, 256>>>(ei);
    k_relu<<<elem_blocks, 256>>>();

    // layer 1
    k_gemm<<<ggemm, 256>>>(x, W, 1);
    k_init_acc<<<elem_blocks, 256>>>(b, 1);
    k_scatter<<<gscat, 256>>>(ei);

    // pooling + final linear
    k_pool_zero<<<(GGG * DD + 255) / 256, 256>>>();
    k_pool<<<(NN + POOL_CHUNK - 1) / POOL_CHUNK, DD>>>(batch);
    k_final<<<1, GGG * CCC>>>(lin_w, lin_b, out);
}

// round 5
// speedup vs baseline: 1.1017x; 1.1017x over previous
#include <cuda_runtime.h>

// Problem constants (fixed by the dataset)
#define NN 50000
#define EE 800000
#define RRR 2
#define DD 128
#define GGG 64
#define CCC 8

// ---------------- device scratch (no allocations allowed) ----------------
__device__ __align__(256) float g_isd[RRR * NN];             // inv_sqrt_deg per relation
__device__ __align__(256) int   g_hist[RRR * NN];            // in-degree histogram
__device__ __align__(256) int   g_rowptr[RRR * (NN + 1)];    // CSR row pointers (by dst)
__device__ __align__(256) int   g_pos[RRR * NN];             // fill cursors
__device__ __align__(256) int   g_csr_src[(size_t)RRR * EE]; // CSR src node ids
__device__ __align__(256) float g_csr_cf[(size_t)RRR * EE];  // per-edge norm coefficient
__device__ __align__(256) float g_xw[(size_t)RRR * NN * DD]; // h @ W[l,r] per relation
__device__ __align__(256) float g_acc[(size_t)NN * DD];      // layer output (layer 1)
__device__ __align__(256) float g_h1[(size_t)NN * DD];       // relu output of layer 0
__device__ __align__(256) float g_pool[GGG * DD];            // per-graph sums
__device__ __align__(256) float g_cnt[GGG];                  // per-graph node counts

// ---------------- CSR build ----------------
__global__ void k_zero_hist() {
    int i = blockIdx.x * blockDim.x + threadIdx.x;
    if (i < RRR * NN) g_hist[i] = 0;
}

__global__ void k_hist(const int* __restrict__ ei) {
    int r = blockIdx.y;
    int e = blockIdx.x * blockDim.x + threadIdx.x;
    if (e < EE) {
        int d = __ldg(ei + (size_t)r * 2 * EE + EE + e);   // dst
        atomicAdd(&g_hist[r * NN + d], 1);
    }
}

// inv_sqrt_deg from histogram (+1 for self loop)
__global__ void k_isd() {
    int i = blockIdx.x * blockDim.x + threadIdx.x;
    if (i < RRR * NN) g_isd[i] = rsqrtf((float)g_hist[i] + 1.0f);
}

// single-block exclusive scan over each relation's histogram -> rowptr & pos
__global__ __launch_bounds__(1024) void k_scan() {
    __shared__ int sh[1024];
    int tid = threadIdx.x;
    for (int r = 0; r < RRR; r++) {
        int run = 0;
        for (int base = 0; base < NN; base += 1024) {
            int i = base + tid;
            int v = (i < NN) ? g_hist[r * NN + i] : 0;
            sh[tid] = v;
            __syncthreads();
#pragma unroll
            for (int off = 1; off < 1024; off <<= 1) {
                int t = (tid >= off) ? sh[tid - off] : 0;
                __syncthreads();
                sh[tid] += t;
                __syncthreads();
            }
            int excl = run + sh[tid] - v;
            if (i < NN) {
                g_rowptr[r * (NN + 1) + i] = excl;
                g_pos[r * NN + i] = excl;
            }
            run += sh[1023];
            __syncthreads();
        }
        if (tid == 0) g_rowptr[r * (NN + 1) + NN] = run;
        __syncthreads();
    }
}

__global__ void k_fill(const int* __restrict__ ei) {
    int r = blockIdx.y;
    int e = blockIdx.x * blockDim.x + threadIdx.x;
    if (e >= EE) return;
    int s = __ldg(ei + (size_t)r * 2 * EE + e);
    int t = __ldg(ei + (size_t)r * 2 * EE + EE + e);
    int p = atomicAdd(&g_pos[r * NN + t], 1);
    g_csr_src[(size_t)r * EE + p] = s;
    g_csr_cf[(size_t)r * EE + p] = g_isd[r * NN + s] * g_isd[r * NN + t];
}

// ---------------- SGEMM: xw[r] = h @ W[l,r]  (fp32, 128x128 tiles) ----------------
#define BM 128
#define BN 128
#define BK 8
#define TM 8
#define TN 8

__global__ __launch_bounds__(256) void k_gemm(const float* __restrict__ x,
                                              const float* __restrict__ W,
                                              int l) {
    __shared__ float As[BK][BM];
    __shared__ float Bs[BK][BN];

    const float* h = (l == 0) ? x : g_h1;
    int r = blockIdx.y;
    const float* Wr = W + ((size_t)(l * 2 + r)) * DD * DD;
    float* out = g_xw + (size_t)r * NN * DD;

    int row0 = blockIdx.x * BM;
    int tid = threadIdx.x;

    int arow = tid >> 1;
    int acol = (tid & 1) * 4;
    int brow = tid >> 5;
    int bcol = (tid & 31) * 4;

    int tm = (tid >> 4) * TM;
    int tn = (tid & 15) * TN;

    float acc[TM][TN];
#pragma unroll
    for (int i = 0; i < TM; i++)
#pragma unroll
        for (int j = 0; j < TN; j++) acc[i][j] = 0.0f;

    for (int k0 = 0; k0 < DD; k0 += BK) {
        int gr = row0 + arow;
        float4 av = make_float4(0.f, 0.f, 0.f, 0.f);
        if (gr < NN) av = *(const float4*)(h + (size_t)gr * DD + k0 + acol);
        As[acol + 0][arow] = av.x;
        As[acol + 1][arow] = av.y;
        As[acol + 2][arow] = av.z;
        As[acol + 3][arow] = av.w;

        float4 bv = *(const float4*)(Wr + (size_t)(k0 + brow) * DD + bcol);
        *(float4*)&Bs[brow][bcol] = bv;

        __syncthreads();

#pragma unroll
        for (int k = 0; k < BK; k++) {
            float4 a0 = *(const float4*)&As[k][tm];
            float4 a1 = *(const float4*)&As[k][tm + 4];
            float4 b0 = *(const float4*)&Bs[k][tn];
            float4 b1 = *(const float4*)&Bs[k][tn + 4];
            float a[TM] = {a0.x, a0.y, a0.z, a0.w, a1.x, a1.y, a1.z, a1.w};
            float b[TN] = {b0.x, b0.y, b0.z, b0.w, b1.x, b1.y, b1.z, b1.w};
#pragma unroll
            for (int i = 0; i < TM; i++)
#pragma unroll
                for (int j = 0; j < TN; j++) acc[i][j] += a[i] * b[j];
        }
        __syncthreads();
    }

#pragma unroll
    for (int i = 0; i < TM; i++) {
        int gr = row0 + tm + i;
        if (gr < NN) {
            float4* p = (float4*)(out + (size_t)gr * DD + tn);
            p[0] = make_float4(acc[i][0], acc[i][1], acc[i][2], acc[i][3]);
            p[1] = make_float4(acc[i][4], acc[i][5], acc[i][6], acc[i][7]);
        }
    }
}

// ---------------- pull aggregation: one warp per dst node ----------------
// acc[node] = sum_r ( sum_{in edges} c * xw_r[src] + isd_r^2 * xw_r[node] + b[l,r] )
// fused relu for layer 0.
__global__ __launch_bounds__(256) void k_pull(const float* __restrict__ b,
                                              int l, int do_relu) {
    int warp = (blockIdx.x * blockDim.x + threadIdx.x) >> 5;
    if (warp >= NN) return;
    int lane = threadIdx.x & 31;
    int node = warp;
    int q = lane * 4;

    // self-loop + biases
    float i0 = g_isd[node];
    float i1 = g_isd[NN + node];
    float c0 = i0 * i0, c1 = i1 * i1;
    float4 v0 = *(const float4*)&g_xw[(size_t)node * DD + q];
    float4 v1 = *(const float4*)&g_xw[((size_t)NN + node) * DD + q];
    const float* b0 = b + (size_t)(l * RRR + 0) * DD + q;
    const float* b1 = b + (size_t)(l * RRR + 1) * DD + q;
    float ax = c0 * v0.x + c1 * v1.x + __ldg(b0 + 0) + __ldg(b1 + 0);
    float ay = c0 * v0.y + c1 * v1.y + __ldg(b0 + 1) + __ldg(b1 + 1);
    float az = c0 * v0.z + c1 * v1.z + __ldg(b0 + 2) + __ldg(b1 + 2);
    float aw = c0 * v0.w + c1 * v1.w + __ldg(b0 + 3) + __ldg(b1 + 3);

#pragma unroll
    for (int r = 0; r < RRR; r++) {
        int beg = g_rowptr[r * (NN + 1) + node];
        int end = g_rowptr[r * (NN + 1) + node + 1];
        const float* xw = g_xw + (size_t)r * NN * DD;
        const int* srcs = g_csr_src + (size_t)r * EE;
        const float* cfs = g_csr_cf + (size_t)r * EE;

        for (int j = beg; j < end; j += 32) {
            int idx = j + lane;
            int s = 0;
            float c = 0.f;
            if (idx < end) {
                s = srcs[idx];
                c = cfs[idx];
            }
            int m = end - j;
            if (m >= 32) {
#pragma unroll 4
                for (int t = 0; t < 32; t++) {
                    int ss = __shfl_sync(0xffffffffu, s, t);
                    float cc = __shfl_sync(0xffffffffu, c, t);
                    float4 v = *(const float4*)&xw[(size_t)ss * DD + q];
                    ax += cc * v.x; ay += cc * v.y;
                    az += cc * v.z; aw += cc * v.w;
                }
            } else {
                for (int t = 0; t < m; t++) {
                    int ss = __shfl_sync(0xffffffffu, s, t);
                    float cc = __shfl_sync(0xffffffffu, c, t);
                    float4 v = *(const float4*)&xw[(size_t)ss * DD + q];
                    ax += cc * v.x; ay += cc * v.y;
                    az += cc * v.z; aw += cc * v.w;
                }
            }
        }
    }

    if (do_relu) {
        ax = fmaxf(ax, 0.f); ay = fmaxf(ay, 0.f);
        az = fmaxf(az, 0.f); aw = fmaxf(aw, 0.f);
        *(float4*)&g_h1[(size_t)node * DD + q] = make_float4(ax, ay, az, aw);
    } else {
        *(float4*)&g_acc[(size_t)node * DD + q] = make_float4(ax, ay, az, aw);
    }
}

// ---------------- pooling ----------------
__global__ void k_pool_zero() {
    int i = blockIdx.x * blockDim.x + threadIdx.x;
    if (i < GGG * DD) g_pool[i] = 0.f;
    if (i < GGG) g_cnt[i] = 0.f;
}

#define POOL_CHUNK 256
__global__ void k_pool(const int* __restrict__ batch) {
    int d = threadIdx.x;                    // 0..127
    int n0 = blockIdx.x * POOL_CHUNK;
    if (n0 >= NN) return;
    int n1 = n0 + POOL_CHUNK;
    if (n1 > NN) n1 = NN;

    int cur = __ldg(batch + n0);
    float local = 0.f;
    float cl = 0.f;
    for (int n = n0; n < n1; n++) {
        int g = __ldg(batch + n);
        if (g != cur) {
            atomicAdd(&g_pool[cur * DD + d], local);
            if (d == 0) atomicAdd(&g_cnt[cur], cl);
            local = 0.f;
            cl = 0.f;
            cur = g;
        }
        local += g_acc[(size_t)n * DD + d];
        cl += 1.f;
    }
    atomicAdd(&g_pool[cur * DD + d], local);
    if (d == 0) atomicAdd(&g_cnt[cur], cl);
}

// ---------------- final linear on pooled means ----------------
__global__ void k_final(const float* __restrict__ lin_w,
                        const float* __restrict__ lin_b,
                        float* __restrict__ out) {
    int tid = threadIdx.x;
    if (tid >= GGG * CCC) return;
    int g = tid >> 3;
    int c = tid & 7;
    float inv = 1.0f / fmaxf(g_cnt[g], 1.0f);
    float s = 0.f;
#pragma unroll 4
    for (int d = 0; d < DD; d++) s += g_pool[g * DD + d] * lin_w[d * CCC + c];
    out[g * CCC + c] = s * inv + lin_b[c];
}

// ---------------- launch ----------------
extern "C" void kernel_launch(void* const* d_in, const int* in_sizes, int n_in,
                              void* d_out, int out_size) {
    const float* x     = (const float*)d_in[0];
    const float* W     = (const float*)d_in[1];
    const float* b     = (const float*)d_in[2];
    const float* lin_w = (const float*)d_in[3];
    const float* lin_b = (const float*)d_in[4];
    const int*   ei    = (const int*)d_in[5];
    const int*   batch = (const int*)d_in[6];
    float* out = (float*)d_out;

    dim3 gE((EE + 255) / 256, RRR);

    // CSR build (by dst) + normalization
    k_zero_hist<<<(RRR * NN + 255) / 256, 256>>>();
    k_hist<<<gE, 256>>>(ei);
    k_isd<<<(RRR * NN + 255) / 256, 256>>>();
    k_scan<<<1, 1024>>>();
    k_fill<<<gE, 256>>>(ei);

    dim3 ggemm((NN + BM - 1) / BM, RRR);
    int pull_blocks = (NN * 32 + 255) / 256;   // one warp per node

    // layer 0
    k_gemm<<<ggemm, 256>>>(x, W, 0);
    k_pull<<<pull_blocks, 256>>>(b, 0, 1);

    // layer 1
    k_gemm<<<ggemm, 256>>>(x, W, 1);
    k_pull<<<pull_blocks, 256>>>(b, 1, 0);

    // pooling + final linear
    k_pool_zero<<<(GGG * DD + 255) / 256, 256>>>();
    k_pool<<<(NN + POOL_CHUNK - 1) / POOL_CHUNK, DD>>>(batch);
    k_final<<<1, GGG * CCC>>>(lin_w, lin_b, out);
}

// round 7
// speedup vs baseline: 1.6152x; 1.4661x over previous
#include <cuda_runtime.h>
#include <cuda_fp16.h>

// Problem constants (fixed by the dataset)
#define NN 50000
#define EE 800000
#define RRR 2
#define DD 128
#define GGG 64
#define CCC 8

#define SCAN_T 1024
#define NTILE ((NN + SCAN_T - 1) / SCAN_T)   // 49

// ---------------- device scratch (no allocations allowed) ----------------
__device__ __align__(256) float g_isd[RRR * NN];              // inv_sqrt_deg per relation
__device__ __align__(256) int   g_hist[RRR * NN];             // in-degree histogram
__device__ __align__(256) int   g_rowptr[RRR * (NN + 1)];     // CSR row pointers (by dst)
__device__ __align__(256) int   g_pos[RRR * NN];              // fill cursors
__device__ __align__(256) int   g_blksum[RRR * NTILE];        // scan block sums
__device__ __align__(256) int   g_blkoff[RRR * NTILE];        // scan block offsets
__device__ __align__(256) int   g_csr_src[(size_t)RRR * EE];  // CSR src node ids
__device__ __align__(256) float g_csr_cf[(size_t)RRR * EE];   // per-edge norm coefficient
__device__ __align__(256) __half g_xwh[(size_t)RRR * NN * DD]; // h @ W[l,r] (fp16)
__device__ __align__(256) float g_acc[(size_t)NN * DD];       // layer output (layer 1)
__device__ __align__(256) float g_h1[(size_t)NN * DD];        // relu output of layer 0
__device__ __align__(256) float g_pool[GGG * DD];             // per-graph sums
__device__ __align__(256) float g_cnt[GGG];                   // per-graph node counts

// ---------------- CSR build ----------------
__global__ void k_zero_hist() {
    int i = blockIdx.x * blockDim.x + threadIdx.x;
    if (i < RRR * NN) g_hist[i] = 0;
}

__global__ void k_hist(const int* __restrict__ ei) {
    int r = blockIdx.y;
    int e = blockIdx.x * blockDim.x + threadIdx.x;
    if (e < EE) {
        int d = __ldg(ei + (size_t)r * 2 * EE + EE + e);   // dst
        atomicAdd(&g_hist[r * NN + d], 1);
    }
}

// inv_sqrt_deg from histogram (+1 for self loop)
__global__ void k_isd() {
    int i = blockIdx.x * blockDim.x + threadIdx.x;
    if (i < RRR * NN) g_isd[i] = rsqrtf((float)g_hist[i] + 1.0f);
}

// ---- hierarchical exclusive scan of g_hist -> g_rowptr / g_pos ----
__global__ __launch_bounds__(256) void k_blocksum() {
    int r = blockIdx.y, blk = blockIdx.x;
    int tid = threadIdx.x;
    int base = blk * SCAN_T + tid * 4;
    int s = 0;
#pragma unroll
    for (int j = 0; j < 4; j++) {
        int i = base + j;
        if (i < NN) s += g_hist[r * NN + i];
    }
#pragma unroll
    for (int off = 16; off > 0; off >>= 1)
        s += __shfl_down_sync(0xffffffffu, s, off);
    __shared__ int ws[8];
    if ((tid & 31) == 0) ws[tid >> 5] = s;
    __syncthreads();
    if (tid == 0) {
        int t = 0;
#pragma unroll
        for (int i = 0; i < 8; i++) t += ws[i];
        g_blksum[r * NTILE + blk] = t;
    }
}

__global__ void k_scanblk() {
    int r = threadIdx.x;
    if (r < RRR) {
        int run = 0;
        for (int i = 0; i < NTILE; i++) {
            g_blkoff[r * NTILE + i] = run;
            run += g_blksum[r * NTILE + i];
        }
        g_rowptr[r * (NN + 1) + NN] = run;   // == EE
    }
}

__global__ __launch_bounds__(SCAN_T) void k_scanwrite() {
    __shared__ int sh[SCAN_T];
    int r = blockIdx.y, blk = blockIdx.x;
    int tid = threadIdx.x;
    int i = blk * SCAN_T + tid;
    int v = (i < NN) ? g_hist[r * NN + i] : 0;
    sh[tid] = v;
    __syncthreads();
#pragma unroll
    for (int off = 1; off < SCAN_T; off <<= 1) {
        int t = (tid >= off) ? sh[tid - off] : 0;
        __syncthreads();
        sh[tid] += t;
        __syncthreads();
    }
    int excl = sh[tid] - v + g_blkoff[r * NTILE + blk];
    if (i < NN) {
        g_rowptr[r * (NN + 1) + i] = excl;
        g_pos[r * NN + i] = excl;
    }
}

__global__ void k_fill(const int* __restrict__ ei) {
    int r = blockIdx.y;
    int e = blockIdx.x * blockDim.x + threadIdx.x;
    if (e >= EE) return;
    int s = __ldg(ei + (size_t)r * 2 * EE + e);
    int t = __ldg(ei + (size_t)r * 2 * EE + EE + e);
    int p = atomicAdd(&g_pos[r * NN + t], 1);
    g_csr_src[(size_t)r * EE + p] = s;
    g_csr_cf[(size_t)r * EE + p] = g_isd[r * NN + s] * g_isd[r * NN + t];
}

// ---------------- SGEMM: xw[r] = h @ W[l,r]  (fp32 accum, fp16 store) ----------------
#define BM 128
#define BN 128
#define BK 8
#define TM 8
#define TN 8

__global__ __launch_bounds__(256) void k_gemm(const float* __restrict__ x,
                                              const float* __restrict__ W,
                                              int l) {
    __shared__ float As[BK][BM];
    __shared__ float Bs[BK][BN];

    const float* h = (l == 0) ? x : g_h1;
    int r = blockIdx.y;
    const float* Wr = W + ((size_t)(l * 2 + r)) * DD * DD;
    __half* out = g_xwh + (size_t)r * NN * DD;

    int row0 = blockIdx.x * BM;
    int tid = threadIdx.x;

    int arow = tid >> 1;
    int acol = (tid & 1) * 4;
    int brow = tid >> 5;
    int bcol = (tid & 31) * 4;

    int tm = (tid >> 4) * TM;
    int tn = (tid & 15) * TN;

    float acc[TM][TN];
#pragma unroll
    for (int i = 0; i < TM; i++)
#pragma unroll
        for (int j = 0; j < TN; j++) acc[i][j] = 0.0f;

    for (int k0 = 0; k0 < DD; k0 += BK) {
        int gr = row0 + arow;
        float4 av = make_float4(0.f, 0.f, 0.f, 0.f);
        if (gr < NN) av = *(const float4*)(h + (size_t)gr * DD + k0 + acol);
        As[acol + 0][arow] = av.x;
        As[acol + 1][arow] = av.y;
        As[acol + 2][arow] = av.z;
        As[acol + 3][arow] = av.w;

        float4 bv = *(const float4*)(Wr + (size_t)(k0 + brow) * DD + bcol);
        *(float4*)&Bs[brow][bcol] = bv;

        __syncthreads();

#pragma unroll
        for (int k = 0; k < BK; k++) {
            float4 a0 = *(const float4*)&As[k][tm];
            float4 a1 = *(const float4*)&As[k][tm + 4];
            float4 b0 = *(const float4*)&Bs[k][tn];
            float4 b1 = *(const float4*)&Bs[k][tn + 4];
            float a[TM] = {a0.x, a0.y, a0.z, a0.w, a1.x, a1.y, a1.z, a1.w};
            float b[TN] = {b0.x, b0.y, b0.z, b0.w, b1.x, b1.y, b1.z, b1.w};
#pragma unroll
            for (int i = 0; i < TM; i++)
#pragma unroll
                for (int j = 0; j < TN; j++) acc[i][j] += a[i] * b[j];
        }
        __syncthreads();
    }

#pragma unroll
    for (int i = 0; i < TM; i++) {
        int gr = row0 + tm + i;
        if (gr < NN) {
            __half2 hv[4];
            hv[0] = __floats2half2_rn(acc[i][0], acc[i][1]);
            hv[1] = __floats2half2_rn(acc[i][2], acc[i][3]);
            hv[2] = __floats2half2_rn(acc[i][4], acc[i][5]);
            hv[3] = __floats2half2_rn(acc[i][6], acc[i][7]);
            *(uint4*)(out + (size_t)gr * DD + tn) = *(uint4*)hv;
        }
    }
}

// ---------------- pull aggregation: one warp per dst node (fp16 gathers) ----------------
__global__ __launch_bounds__(256) void k_pull(const float* __restrict__ b,
                                              int l, int do_relu) {
    int warp = (blockIdx.x * blockDim.x + threadIdx.x) >> 5;
    if (warp >= NN) return;
    int lane = threadIdx.x & 31;
    int node = warp;
    int q = lane * 4;

    // self-loop + biases
    float i0 = g_isd[node];
    float i1 = g_isd[NN + node];
    float c0 = i0 * i0, c1 = i1 * i1;

    uint2 raw0 = *(const uint2*)(g_xwh + (size_t)node * DD + q);
    uint2 raw1 = *(const uint2*)(g_xwh + ((size_t)NN + node) * DD + q);
    float2 s0a = __half22float2(*(__half2*)&raw0.x);
    float2 s0b = __half22float2(*(__half2*)&raw0.y);
    float2 s1a = __half22float2(*(__half2*)&raw1.x);
    float2 s1b = __half22float2(*(__half2*)&raw1.y);

    const float* b0 = b + (size_t)(l * RRR + 0) * DD + q;
    const float* b1 = b + (size_t)(l * RRR + 1) * DD + q;
    float ax = c0 * s0a.x + c1 * s1a.x + __ldg(b0 + 0) + __ldg(b1 + 0);
    float ay = c0 * s0a.y + c1 * s1a.y + __ldg(b0 + 1) + __ldg(b1 + 1);
    float az = c0 * s0b.x + c1 * s1b.x + __ldg(b0 + 2) + __ldg(b1 + 2);
    float aw = c0 * s0b.y + c1 * s1b.y + __ldg(b0 + 3) + __ldg(b1 + 3);

#pragma unroll
    for (int r = 0; r < RRR; r++) {
        int beg = g_rowptr[r * (NN + 1) + node];
        int end = g_rowptr[r * (NN + 1) + node + 1];
        const __half* xw = g_xwh + (size_t)r * NN * DD;
        const int* srcs = g_csr_src + (size_t)r * EE;
        const float* cfs = g_csr_cf + (size_t)r * EE;

        for (int j = beg; j < end; j += 32) {
            int idx = j + lane;
            int s = 0;
            float c = 0.f;
            if (idx < end) {
                s = srcs[idx];
                c = cfs[idx];
            }
            int m = end - j;
            if (m >= 32) {
#pragma unroll 4
                for (int t = 0; t < 32; t++) {
                    int ss = __shfl_sync(0xffffffffu, s, t);
                    float cc = __shfl_sync(0xffffffffu, c, t);
                    uint2 rw = *(const uint2*)(xw + (size_t)ss * DD + q);
                    float2 fa = __half22float2(*(__half2*)&rw.x);
                    float2 fb = __half22float2(*(__half2*)&rw.y);
                    ax += cc * fa.x; ay += cc * fa.y;
                    az += cc * fb.x; aw += cc * fb.y;
                }
            } else {
                for (int t = 0; t < m; t++) {
                    int ss = __shfl_sync(0xffffffffu, s, t);
                    float cc = __shfl_sync(0xffffffffu, c, t);
                    uint2 rw = *(const uint2*)(xw + (size_t)ss * DD + q);
                    float2 fa = __half22float2(*(__half2*)&rw.x);
                    float2 fb = __half22float2(*(__half2*)&rw.y);
                    ax += cc * fa.x; ay += cc * fa.y;
                    az += cc * fb.x; aw += cc * fb.y;
                }
            }
        }
    }

    if (do_relu) {
        ax = fmaxf(ax, 0.f); ay = fmaxf(ay, 0.f);
        az = fmaxf(az, 0.f); aw = fmaxf(aw, 0.f);
        *(float4*)&g_h1[(size_t)node * DD + q] = make_float4(ax, ay, az, aw);
    } else {
        *(float4*)&g_acc[(size_t)node * DD + q] = make_float4(ax, ay, az, aw);
    }
}

// ---------------- pooling ----------------
__global__ void k_pool_zero() {
    int i = blockIdx.x * blockDim.x + threadIdx.x;
    if (i < GGG * DD) g_pool[i] = 0.f;
    if (i < GGG) g_cnt[i] = 0.f;
}

#define POOL_CHUNK 256
__global__ void k_pool(const int* __restrict__ batch) {
    int d = threadIdx.x;                    // 0..127
    int n0 = blockIdx.x * POOL_CHUNK;
    if (n0 >= NN) return;
    int n1 = n0 + POOL_CHUNK;
    if (n1 > NN) n1 = NN;

    int cur = __ldg(batch + n0);
    float local = 0.f;
    float cl = 0.f;
    for (int n = n0; n < n1; n++) {
        int g = __ldg(batch + n);
        if (g != cur) {
            atomicAdd(&g_pool[cur * DD + d], local);
            if (d == 0) atomicAdd(&g_cnt[cur], cl);
            local = 0.f;
            cl = 0.f;
            cur = g;
        }
        local += g_acc[(size_t)n * DD + d];
        cl += 1.f;
    }
    atomicAdd(&g_pool[cur * DD + d], local);
    if (d == 0) atomicAdd(&g_cnt[cur], cl);
}

// ---------------- final linear on pooled means ----------------
__global__ void k_final(const float* __restrict__ lin_w,
                        const float* __restrict__ lin_b,
                        float* __restrict__ out) {
    int tid = threadIdx.x;
    if (tid >= GGG * CCC) return;
    int g = tid >> 3;
    int c = tid & 7;
    float inv = 1.0f / fmaxf(g_cnt[g], 1.0f);
    float s = 0.f;
#pragma unroll 4
    for (int d = 0; d < DD; d++) s += g_pool[g * DD + d] * lin_w[d * CCC + c];
    out[g * CCC + c] = s * inv + lin_b[c];
}

// ---------------- launch ----------------
extern "C" void kernel_launch(void* const* d_in, const int* in_sizes, int n_in,
                              void* d_out, int out_size) {
    const float* x     = (const float*)d_in[0];
    const float* W     = (const float*)d_in[1];
    const float* b     = (const float*)d_in[2];
    const float* lin_w = (const float*)d_in[3];
    const float* lin_b = (const float*)d_in[4];
    const int*   ei    = (const int*)d_in[5];
    const int*   batch = (const int*)d_in[6];
    float* out = (float*)d_out;

    dim3 gE((EE + 255) / 256, RRR);
    dim3 gTile(NTILE, RRR);

    // CSR build (by dst) + normalization
    k_zero_hist<<<(RRR * NN + 255) / 256, 256>>>();
    k_hist<<<gE, 256>>>(ei);
    k_isd<<<(RRR * NN + 255) / 256, 256>>>();
    k_blocksum<<<gTile, 256>>>();
    k_scanblk<<<1, 32>>>();
    k_scanwrite<<<gTile, SCAN_T>>>();
    k_fill<<<gE, 256>>>(ei);

    dim3 ggemm((NN + BM - 1) / BM, RRR);
    int pull_blocks = (NN * 32 + 255) / 256;   // one warp per node

    // layer 0
    k_gemm<<<ggemm, 256>>>(x, W, 0);
    k_pull<<<pull_blocks, 256>>>(b, 0, 1);

    // layer 1
    k_gemm<<<ggemm, 256>>>(x, W, 1);
    k_pull<<<pull_blocks, 256>>>(b, 1, 0);

    // pooling + final linear
    k_pool_zero<<<(GGG * DD + 255) / 256, 256>>>();
    k_pool<<<(NN + POOL_CHUNK - 1) / POOL_CHUNK, DD>>>(batch);
    k_final<<<1, GGG * CCC>>>(lin_w, lin_b, out);
}